// round 11
// baseline (speedup 1.0000x reference)
#include <cuda_runtime.h>
#include <cuda_fp16.h>

// Problem constants (fixed shapes per reference)
#define NN 100000
#define EE 1600000
#define FIN 32
#define FHID 64
#define FOUT 32

#define SCAN_B 512
#define NB_MAX 256     // ceil(100000/512)=196 <= 256
#define TILE_W 8       // nodes per warp in k_mlp
#define AGG_CTAS 1216  // single co-resident wave: 8 CTAs/SM x 152 SMs
#define AGG_WARPS (AGG_CTAS * 8)

// Scratch (device globals — referenced ONLY from device code; host-side use of
// these symbols resolves to the host shadow object on GB300/ATS).
__device__ int    g_deg[NN];
__device__ int    g_rowptr[NN];        // block-local exclusive prefix of deg
__device__ int    g_cur[NN];           // fill cursor, initialized = g_rowptr
__device__ int    g_bsum[NB_MAX];      // per-block sums -> exclusive after last-block scan
__device__ float  g_dinv[NN];
__device__ int    g_col[EE];
__device__ int    g_scan_done = 0;     // last-block ticket (self-resetting)
__device__ __align__(16) __half g_xsh[NN * FIN];        // dinv[v]*x[v]   (fp16)
__device__ __align__(16) __half g_gsh[NN * FOUT];       // dinv[v]*(h@W2) (fp16)
__device__ __align__(16) float  g_ax[(NN + 64) * FIN];  // dinv*(agg xs)  (fp32, padded)

// packed f32x2 helpers
#define FMA2(d, a, b, c) \
    asm("fma.rn.f32x2 %0, %1, %2, %3;" : "=l"(d) : "l"(a), "l"(b), "l"(c))
__device__ __forceinline__ unsigned long long pk2(float a, float b) {
    float2 t = make_float2(a, b);
    return *(unsigned long long*)&t;
}
__device__ __forceinline__ unsigned long long dup2(float a) {
    unsigned long long r;
    asm("mov.b64 %0, {%1, %1};" : "=l"(r) : "r"(__float_as_uint(a)));
    return r;
}
__device__ __forceinline__ float lo2(unsigned long long v) {
    return __uint_as_float((unsigned)(v & 0xffffffffull));
}
__device__ __forceinline__ float hi2(unsigned long long v) {
    return __uint_as_float((unsigned)(v >> 32));
}

// ---------------------------------------------------------------------------
// Per-warp inline probe: which of {c0,c1} is edge_index? Edge words are
// unsigned < 100000; fp32 normal bit patterns are >= 2^23 or have sign bit.
__device__ __forceinline__ int probe_is_edges(const void* c0) {
    unsigned idx = (threadIdx.x & 31) * 99991u + (blockIdx.x & 1023) * 131u;
    unsigned v = ((const unsigned*)c0)[idx];  // < 3.2M
    return __all_sync(0xffffffffu, v < 100000u);
}

// ---- degree count: 4 edges per thread (int4) ------------------------------
__global__ void k_count(const void* c0, const void* c1, int e) {
    const int* eptr = probe_is_edges(c0) ? (const int*)c0 : (const int*)c1;
    int i = (blockIdx.x * blockDim.x + threadIdx.x) * 4;
    if (i < e) {
        int4 d4 = *(const int4*)(eptr + e + i);
        if ((unsigned)d4.x < (unsigned)NN) atomicAdd(&g_deg[d4.x], 1);
        if ((unsigned)d4.y < (unsigned)NN) atomicAdd(&g_deg[d4.y], 1);
        if ((unsigned)d4.z < (unsigned)NN) atomicAdd(&g_deg[d4.z], 1);
        if ((unsigned)d4.w < (unsigned)NN) atomicAdd(&g_deg[d4.w], 1);
    }
}

// ---- scan: block-exclusive scan of deg + dinv + fp16 pre-scale; the last
// block to finish also scans the 196 block sums (fused scanB).
__global__ __launch_bounds__(SCAN_B) void k_scan(const void* c0, const void* c1,
                                                 int n, int nb) {
    const float* xptr = probe_is_edges(c0) ? (const float*)c1 : (const float*)c0;
    __shared__ int   s[SCAN_B];
    __shared__ float sdinv[SCAN_B];
    __shared__ int   sB[NB_MAX];
    __shared__ bool  amLast;
    int t = threadIdx.x;
    int i = blockIdx.x * SCAN_B + t;
    int v = (i < n) ? g_deg[i] : 0;
    s[t] = v;
    __syncthreads();
    for (int o = 1; o < SCAN_B; o <<= 1) {
        int x = (t >= o) ? s[t - o] : 0;
        __syncthreads();
        s[t] += x;
        __syncthreads();
    }
    float d = rsqrtf((float)(v + 1));          // +1 self-loop
    if (i < n) {
        int excl = s[t] - v;
        g_rowptr[i] = excl;
        g_cur[i] = excl;                        // fill cursor
        g_dinv[i] = d;
    }
    sdinv[t] = d;
    if (t == SCAN_B - 1) g_bsum[blockIdx.x] = s[t];
    __syncthreads();

    // pre-scale: nodes [b0, b0+512) -> fp16 rows (4096 quads, 8 iters)
    int b0 = blockIdx.x * SCAN_B;
#pragma unroll
    for (int r = 0; r < 8; r++) {
        int ql = t + r * SCAN_B;               // local quad 0..4095
        int nl = ql >> 3;                      // local node
        int node = b0 + nl;
        if (node < n) {
            float4 p = ((const float4*)xptr)[node * 8 + (ql & 7)];
            float dd = sdinv[nl];
            __half2 h0 = __floats2half2_rn(p.x * dd, p.y * dd);
            __half2 h1 = __floats2half2_rn(p.z * dd, p.w * dd);
            uint2 packed;
            packed.x = *(unsigned*)&h0;
            packed.y = *(unsigned*)&h1;
            ((uint2*)g_xsh)[node * 8 + (ql & 7)] = packed;
        }
    }

    // last-block: exclusive scan of the nb block sums
    __threadfence();
    __syncthreads();
    if (t == 0) amLast = (atomicAdd(&g_scan_done, 1) == gridDim.x - 1);
    __syncthreads();
    if (amLast) {
        __threadfence();                        // acquire all bsum writes
        int bv = (t < NB_MAX && t < nb) ? g_bsum[t] : 0;
        if (t < NB_MAX) sB[t] = bv;
        __syncthreads();
        for (int o = 1; o < NB_MAX; o <<= 1) {
            int x = (t >= o && t < NB_MAX) ? sB[t - o] : 0;
            __syncthreads();
            if (t < NB_MAX) sB[t] += x;
            __syncthreads();
        }
        if (t < nb) g_bsum[t] = sB[t] - bv;     // exclusive block offsets
        if (t == 0) g_scan_done = 0;            // reset for next graph replay
    }
}

// global rowptr on the fly
__device__ __forceinline__ int rp(int i, int e) {
    return (i == NN) ? e : (g_rowptr[i] + g_bsum[i >> 9]);
}

// ---- CSR bucket fill: 4 edges per thread ----------------------------------
__global__ void k_fill(const void* c0, const void* c1, int e) {
    const int* eptr = probe_is_edges(c0) ? (const int*)c0 : (const int*)c1;
    int i = (blockIdx.x * blockDim.x + threadIdx.x) * 4;
    if (i < e) {
        int4 s4 = *(const int4*)(eptr + i);
        int4 d4 = *(const int4*)(eptr + e + i);
        if ((unsigned)d4.x < (unsigned)NN)
            g_col[atomicAdd(&g_cur[d4.x], 1) + g_bsum[d4.x >> 9]] = s4.x;
        if ((unsigned)d4.y < (unsigned)NN)
            g_col[atomicAdd(&g_cur[d4.y], 1) + g_bsum[d4.y >> 9]] = s4.y;
        if ((unsigned)d4.z < (unsigned)NN)
            g_col[atomicAdd(&g_cur[d4.z], 1) + g_bsum[d4.z >> 9]] = s4.z;
        if ((unsigned)d4.w < (unsigned)NN)
            g_col[atomicAdd(&g_cur[d4.w], 1) + g_bsum[d4.w >> 9]] = s4.w;
    }
}

// ---- fp16 warp aggregation core (R8 form): 8 edges in flight per iter -----
// Warp = node v. lane = eslot(2b)<<3 | fq(3b). After reduce, lanes 0..7 hold
// quad fq of  sum_{u in N(v)} in[u] + in[v]   (inputs pre-scaled by dinv[u]).
__device__ __forceinline__ float4 aggh(const __half* __restrict__ in,
                                       int v, int lane, int beg, int end) {
    int eslot = lane >> 3;
    int fq = lane & 7;
    float4 acc = make_float4(0.f, 0.f, 0.f, 0.f);
    for (int k = beg; k < end; k += 8) {
        int i0 = k + eslot;
        int i1 = i0 + 4;
        int u0 = (i0 < end) ? g_col[i0] : -1;
        int u1 = (i1 < end) ? g_col[i1] : -1;
        if (u0 >= 0) {
            uint2 raw = *(const uint2*)(in + u0 * 32 + fq * 4);
            float2 fa = __half22float2(*(__half2*)&raw.x);
            float2 fb = __half22float2(*(__half2*)&raw.y);
            acc.x += fa.x; acc.y += fa.y; acc.z += fb.x; acc.w += fb.y;
        }
        if (u1 >= 0) {
            uint2 raw = *(const uint2*)(in + u1 * 32 + fq * 4);
            float2 fa = __half22float2(*(__half2*)&raw.x);
            float2 fb = __half22float2(*(__half2*)&raw.y);
            acc.x += fa.x; acc.y += fa.y; acc.z += fb.x; acc.w += fb.y;
        }
    }
    if (eslot == 0) {   // self-loop
        uint2 raw = *(const uint2*)(in + v * 32 + fq * 4);
        float2 fa = __half22float2(*(__half2*)&raw.x);
        float2 fb = __half22float2(*(__half2*)&raw.y);
        acc.x += fa.x; acc.y += fa.y; acc.z += fb.x; acc.w += fb.y;
    }
#pragma unroll
    for (int d = 16; d >= 8; d >>= 1) {
        acc.x += __shfl_down_sync(0xffffffffu, acc.x, d);
        acc.y += __shfl_down_sync(0xffffffffu, acc.y, d);
        acc.z += __shfl_down_sync(0xffffffffu, acc.z, d);
        acc.w += __shfl_down_sync(0xffffffffu, acc.w, d);
    }
    return acc;
}

// ---- agg1: persistent single-wave gather: ax = dinv*(agg xs) --------------
// Each warp sweeps a contiguous chunk of nodes; cross-node ILP fills the
// load pipeline and there are no wave transitions (grid = 1 wave).
__global__ __launch_bounds__(256) void k_agg1(int n, int e) {
    int wg = (blockIdx.x * blockDim.x + threadIdx.x) >> 5;
    int lane = threadIdx.x & 31;
    int chunk = (n + AGG_WARPS - 1) / AGG_WARPS;
    int v0 = wg * chunk;
    int v1 = min(v0 + chunk, n);
    for (int v = v0; v < v1; v++) {
        float4 acc = aggh(g_xsh, v, lane, rp(v, e), rp(v + 1, e));
        if (lane < 8) {
            float dv = g_dinv[v];
            float4 r;
            r.x = dv * acc.x; r.y = dv * acc.y;
            r.z = dv * acc.z; r.w = dv * acc.w;
            *(float4*)&g_ax[v * 32 + lane * 4] = r;
        }
    }
}

// ---- mlp: dedicated, warp owns TILE_W nodes; weights in regs (phased so
// w1p/w2p lifetimes are disjoint); activations via conflict-free LDS.128
// broadcasts. gs = dinv*(relu(ax@W1+b1)@W2) -> fp16.
__global__ __launch_bounds__(256) void k_mlp(const float* __restrict__ W1,
                                             const float* __restrict__ b1,
                                             const float* __restrict__ W2,
                                             int n) {
    __shared__ __align__(16) float s_ax[8][TILE_W][FIN];
    __shared__ __align__(16) float s_h[8][TILE_W][FHID];

    int wl = threadIdx.x >> 5;
    int lane = threadIdx.x & 31;
    int base = (blockIdx.x * 8 + wl) * TILE_W;
    if (base >= n) return;

    // --- A: stage 8 node rows (g_ax is padded; OOB rows unused) ---
    {
        const float4* src = (const float4*)(g_ax + base * 32);
        float4* dst = (float4*)s_ax[wl];
        dst[lane]      = src[lane];
        dst[lane + 32] = src[lane + 32];
    }
    __syncwarp();

    // --- B: layer 1, weight column-pair (lane, lane+32) in registers ---
    {
        unsigned long long w1p[32];
#pragma unroll
        for (int i = 0; i < 32; i++)
            w1p[i] = pk2(W1[i * 64 + lane], W1[i * 64 + 32 + lane]);
        unsigned long long bpair = pk2(b1[lane], b1[lane + 32]);

#pragma unroll 1
        for (int j = 0; j < TILE_W; j++) {
            if (base + j >= n) break;
            unsigned long long acc = bpair;
            const float4* axv = (const float4*)s_ax[wl][j];
#pragma unroll
            for (int i4 = 0; i4 < 8; i4++) {
                float4 x4 = axv[i4];          // LDS.128 broadcast
                FMA2(acc, dup2(x4.x), w1p[i4 * 4 + 0], acc);
                FMA2(acc, dup2(x4.y), w1p[i4 * 4 + 1], acc);
                FMA2(acc, dup2(x4.z), w1p[i4 * 4 + 2], acc);
                FMA2(acc, dup2(x4.w), w1p[i4 * 4 + 3], acc);
            }
            s_h[wl][j][lane]      = fmaxf(lo2(acc), 0.f);
            s_h[wl][j][lane + 32] = fmaxf(hi2(acc), 0.f);
        }
    }
    __syncwarp();

    // --- C: layer 2, weight row-pair (2i, 2i+1) column lane in registers ---
    {
        unsigned long long w2p[32];
#pragma unroll
        for (int i = 0; i < 32; i++)
            w2p[i] = pk2(W2[(2 * i) * 32 + lane], W2[(2 * i + 1) * 32 + lane]);

#pragma unroll 1
        for (int j = 0; j < TILE_W; j++) {
            int v = base + j;
            if (v >= n) break;
            unsigned long long acc = 0;
            const float4* hv = (const float4*)s_h[wl][j];
#pragma unroll
            for (int i4 = 0; i4 < 16; i4++) {
                float4 h4 = hv[i4];           // LDS.128 broadcast
                FMA2(acc, pk2(h4.x, h4.y), w2p[2 * i4 + 0], acc);
                FMA2(acc, pk2(h4.z, h4.w), w2p[2 * i4 + 1], acc);
            }
            float o = lo2(acc) + hi2(acc);
            g_gsh[v * 32 + lane] = __float2half_rn(g_dinv[v] * o);
        }
    }
}

// ---- layer 2: persistent single-wave: out = dinv*(agg gs) + b2 ------------
__global__ __launch_bounds__(256) void k_l2(float* __restrict__ out,
                                            const float* __restrict__ b2,
                                            int n, int e) {
    int wg = (blockIdx.x * blockDim.x + threadIdx.x) >> 5;
    int lane = threadIdx.x & 31;
    int chunk = (n + AGG_WARPS - 1) / AGG_WARPS;
    int v0 = wg * chunk;
    int v1 = min(v0 + chunk, n);
    for (int v = v0; v < v1; v++) {
        float4 acc = aggh(g_gsh, v, lane, rp(v, e), rp(v + 1, e));
        if (lane < 8) {
            float dv = g_dinv[v];
            float4 bq = *(const float4*)(b2 + lane * 4);
            float4 r;
            r.x = dv * acc.x + bq.x;
            r.y = dv * acc.y + bq.y;
            r.z = dv * acc.z + bq.z;
            r.w = dv * acc.w + bq.w;
            *(float4*)(out + v * 32 + lane * 4) = r;
        }
    }
}

// ---------------------------------------------------------------------------
extern "C" void kernel_launch(void* const* d_in, const int* in_sizes, int n_in,
                              void* d_out, int out_size) {
    // Resolve by element count: 3.2M x2 {x, edge_index} (probed on-device);
    // 2048 x2 W1 then W2; 64 b1; 32 b2.
    const void* big[2] = {nullptr, nullptr}; int nbig = 0;
    const float* W[2] = {nullptr, nullptr};  int nw = 0;
    const float* b1 = nullptr;
    const float* b2 = nullptr;
    for (int i = 0; i < n_in; i++) {
        int s = in_sizes[i];
        if (s == NN * FIN) { if (nbig < 2) big[nbig++] = d_in[i]; }
        else if (s == FIN * FHID) { if (nw < 2) W[nw++] = (const float*)d_in[i]; }
        else if (s == FHID) b1 = (const float*)d_in[i];
        else if (s == FOUT) b2 = (const float*)d_in[i];
    }
    const float* W1 = W[0];
    const float* W2 = W[1];
    float* out = (float*)d_out;

    const int n = NN;
    const int e = EE;
    int nb = (n + SCAN_B - 1) / SCAN_B;   // 196

    // zero g_deg via memset node (true device address, NOT the host shadow)
    void* degAddr = nullptr;
    cudaGetSymbolAddress(&degAddr, g_deg);
    cudaMemsetAsync(degAddr, 0, NN * sizeof(int));

    int eThreads = e / 4;
    k_count<<<(eThreads + 255) / 256, 256>>>(big[0], big[1], e);
    k_scan<<<nb, SCAN_B>>>(big[0], big[1], n, nb);
    k_fill<<<(eThreads + 255) / 256, 256>>>(big[0], big[1], e);

    k_agg1<<<AGG_CTAS, 256>>>(n, e);
    int mlpGrid = (n + 8 * TILE_W - 1) / (8 * TILE_W);  // 64 nodes per CTA
    k_mlp<<<mlpGrid, 256>>>(W1, b1, W2, n);
    k_l2<<<AGG_CTAS, 256>>>(out, b2, n, e);
}

// round 12
// speedup vs baseline: 1.4407x; 1.4407x over previous
#include <cuda_runtime.h>
#include <cuda_fp16.h>

// Problem constants (fixed shapes per reference)
#define NN 100000
#define EE 1600000
#define FIN 32
#define FHID 64
#define FOUT 32

#define SCAN_B 512
#define NB_MAX 256   // ceil(100000/512)=196 <= 256
#define TILE_W 8     // nodes per warp in k_mlp

// Scratch (device globals — referenced ONLY from device code; host-side use of
// these symbols resolves to the host shadow object on GB300/ATS).
__device__ int    g_deg[NN];
__device__ int    g_rowptr[NN];        // block-local exclusive prefix of deg
__device__ int    g_cur[NN];           // fill cursor, initialized = g_rowptr
__device__ int    g_bsum[NB_MAX];      // per-block sums -> exclusive after last-block scan
__device__ float  g_dinv[NN];
__device__ int    g_col[EE];
__device__ int    g_scan_done = 0;     // last-block ticket (self-resetting)
__device__ __align__(16) __half g_xsh[NN * FIN];        // dinv[v]*x[v]   (fp16)
__device__ __align__(16) __half g_gsh[NN * FOUT];       // dinv[v]*(h@W2) (fp16)
__device__ __align__(16) float  g_ax[(NN + 64) * FIN];  // dinv*(agg xs)  (fp32, padded)

// packed f32x2 helpers
#define FMA2(d, a, b, c) \
    asm("fma.rn.f32x2 %0, %1, %2, %3;" : "=l"(d) : "l"(a), "l"(b), "l"(c))
__device__ __forceinline__ unsigned long long pk2(float a, float b) {
    float2 t = make_float2(a, b);
    return *(unsigned long long*)&t;
}
__device__ __forceinline__ unsigned long long dup2(float a) {
    unsigned long long r;
    asm("mov.b64 %0, {%1, %1};" : "=l"(r) : "r"(__float_as_uint(a)));
    return r;
}
__device__ __forceinline__ float lo2(unsigned long long v) {
    return __uint_as_float((unsigned)(v & 0xffffffffull));
}
__device__ __forceinline__ float hi2(unsigned long long v) {
    return __uint_as_float((unsigned)(v >> 32));
}

// ---------------------------------------------------------------------------
// Per-warp inline probe: which of {c0,c1} is edge_index? Edge words are
// unsigned < 100000; fp32 normal bit patterns are >= 2^23 or have sign bit.
__device__ __forceinline__ int probe_is_edges(const void* c0) {
    unsigned idx = (threadIdx.x & 31) * 99991u + (blockIdx.x & 1023) * 131u;
    unsigned v = ((const unsigned*)c0)[idx];  // < 3.2M
    return __all_sync(0xffffffffu, v < 100000u);
}

// ---- degree count: 4 edges per thread (int4) ------------------------------
__global__ void k_count(const void* c0, const void* c1, int e) {
    const int* eptr = probe_is_edges(c0) ? (const int*)c0 : (const int*)c1;
    int i = (blockIdx.x * blockDim.x + threadIdx.x) * 4;
    if (i < e) {
        int4 d4 = *(const int4*)(eptr + e + i);
        if ((unsigned)d4.x < (unsigned)NN) atomicAdd(&g_deg[d4.x], 1);
        if ((unsigned)d4.y < (unsigned)NN) atomicAdd(&g_deg[d4.y], 1);
        if ((unsigned)d4.z < (unsigned)NN) atomicAdd(&g_deg[d4.z], 1);
        if ((unsigned)d4.w < (unsigned)NN) atomicAdd(&g_deg[d4.w], 1);
    }
}

// ---- scan: block-exclusive scan of deg + dinv + fp16 pre-scale; the last
// block to finish also scans the 196 block sums (fused scanB).
__global__ __launch_bounds__(SCAN_B) void k_scan(const void* c0, const void* c1,
                                                 int n, int nb) {
    const float* xptr = probe_is_edges(c0) ? (const float*)c1 : (const float*)c0;
    __shared__ int   s[SCAN_B];
    __shared__ float sdinv[SCAN_B];
    __shared__ int   sB[NB_MAX];
    __shared__ bool  amLast;
    int t = threadIdx.x;
    int i = blockIdx.x * SCAN_B + t;
    int v = (i < n) ? g_deg[i] : 0;
    s[t] = v;
    __syncthreads();
    for (int o = 1; o < SCAN_B; o <<= 1) {
        int x = (t >= o) ? s[t - o] : 0;
        __syncthreads();
        s[t] += x;
        __syncthreads();
    }
    float d = rsqrtf((float)(v + 1));          // +1 self-loop
    if (i < n) {
        int excl = s[t] - v;
        g_rowptr[i] = excl;
        g_cur[i] = excl;                        // fill cursor
        g_dinv[i] = d;
    }
    sdinv[t] = d;
    if (t == SCAN_B - 1) g_bsum[blockIdx.x] = s[t];
    __syncthreads();

    // pre-scale: nodes [b0, b0+512) -> fp16 rows (4096 quads, 8 iters)
    int b0 = blockIdx.x * SCAN_B;
#pragma unroll
    for (int r = 0; r < 8; r++) {
        int ql = t + r * SCAN_B;               // local quad 0..4095
        int nl = ql >> 3;                      // local node
        int node = b0 + nl;
        if (node < n) {
            float4 p = ((const float4*)xptr)[node * 8 + (ql & 7)];
            float dd = sdinv[nl];
            __half2 h0 = __floats2half2_rn(p.x * dd, p.y * dd);
            __half2 h1 = __floats2half2_rn(p.z * dd, p.w * dd);
            uint2 packed;
            packed.x = *(unsigned*)&h0;
            packed.y = *(unsigned*)&h1;
            ((uint2*)g_xsh)[node * 8 + (ql & 7)] = packed;
        }
    }

    // last-block: exclusive scan of the nb block sums
    __threadfence();
    __syncthreads();
    if (t == 0) amLast = (atomicAdd(&g_scan_done, 1) == gridDim.x - 1);
    __syncthreads();
    if (amLast) {
        __threadfence();                        // acquire all bsum writes
        int bv = (t < NB_MAX && t < nb) ? g_bsum[t] : 0;
        if (t < NB_MAX) sB[t] = bv;
        __syncthreads();
        for (int o = 1; o < NB_MAX; o <<= 1) {
            int x = (t >= o && t < NB_MAX) ? sB[t - o] : 0;
            __syncthreads();
            if (t < NB_MAX) sB[t] += x;
            __syncthreads();
        }
        if (t < nb) g_bsum[t] = sB[t] - bv;     // exclusive block offsets
        if (t == 0) g_scan_done = 0;            // reset for next graph replay
    }
}

// global rowptr on the fly
__device__ __forceinline__ int rp(int i, int e) {
    return (i == NN) ? e : (g_rowptr[i] + g_bsum[i >> 9]);
}

// ---- CSR bucket fill: 4 edges per thread ----------------------------------
__global__ void k_fill(const void* c0, const void* c1, int e) {
    const int* eptr = probe_is_edges(c0) ? (const int*)c0 : (const int*)c1;
    int i = (blockIdx.x * blockDim.x + threadIdx.x) * 4;
    if (i < e) {
        int4 s4 = *(const int4*)(eptr + i);
        int4 d4 = *(const int4*)(eptr + e + i);
        if ((unsigned)d4.x < (unsigned)NN)
            g_col[atomicAdd(&g_cur[d4.x], 1) + g_bsum[d4.x >> 9]] = s4.x;
        if ((unsigned)d4.y < (unsigned)NN)
            g_col[atomicAdd(&g_cur[d4.y], 1) + g_bsum[d4.y >> 9]] = s4.y;
        if ((unsigned)d4.z < (unsigned)NN)
            g_col[atomicAdd(&g_cur[d4.z], 1) + g_bsum[d4.z >> 9]] = s4.z;
        if ((unsigned)d4.w < (unsigned)NN)
            g_col[atomicAdd(&g_cur[d4.w], 1) + g_bsum[d4.w >> 9]] = s4.w;
    }
}

// ---- fp16 warp aggregation core, BRANCH-FREE -------------------------------
// Warp = node v. lane = eslot(2b)<<3 | fq(3b). 8 edges per iteration; OOB
// slots are index-clamped to a valid address and their bytes masked to zero
// (no BSSY/BSYNC, no divergent branches). Self-loop is also mask-predicated.
// After reduce, lanes 0..7 hold quad fq of sum_{u in N(v)} in[u] + in[v].
__device__ __forceinline__ float4 aggh(const __half* __restrict__ in,
                                       int v, int lane, int beg, int end) {
    int eslot = lane >> 3;
    int fq = lane & 7;
    float4 acc = make_float4(0.f, 0.f, 0.f, 0.f);
    int last = end - 1;
    for (int k = beg; k < end; k += 8) {
        int i0 = k + eslot;
        int i1 = i0 + 4;
        int u0 = g_col[min(i0, last)];
        int u1 = g_col[min(i1, last)];
        uint2 r0 = *(const uint2*)(in + u0 * 32 + fq * 4);
        uint2 r1 = *(const uint2*)(in + u1 * 32 + fq * 4);
        unsigned m0 = (i0 <= last) ? 0xffffffffu : 0u;
        unsigned m1 = (i1 <= last) ? 0xffffffffu : 0u;
        r0.x &= m0; r0.y &= m0;
        r1.x &= m1; r1.y &= m1;
        float2 fa0 = __half22float2(*(__half2*)&r0.x);
        float2 fb0 = __half22float2(*(__half2*)&r0.y);
        float2 fa1 = __half22float2(*(__half2*)&r1.x);
        float2 fb1 = __half22float2(*(__half2*)&r1.y);
        acc.x += fa0.x; acc.y += fa0.y; acc.z += fb0.x; acc.w += fb0.y;
        acc.x += fa1.x; acc.y += fa1.y; acc.z += fb1.x; acc.w += fb1.y;
    }
    {   // self-loop: always load (valid address), mask by eslot==0
        uint2 raw = *(const uint2*)(in + v * 32 + fq * 4);
        unsigned ms = (eslot == 0) ? 0xffffffffu : 0u;
        raw.x &= ms; raw.y &= ms;
        float2 fa = __half22float2(*(__half2*)&raw.x);
        float2 fb = __half22float2(*(__half2*)&raw.y);
        acc.x += fa.x; acc.y += fa.y; acc.z += fb.x; acc.w += fb.y;
    }
#pragma unroll
    for (int d = 16; d >= 8; d >>= 1) {
        acc.x += __shfl_down_sync(0xffffffffu, acc.x, d);
        acc.y += __shfl_down_sync(0xffffffffu, acc.y, d);
        acc.z += __shfl_down_sync(0xffffffffu, acc.z, d);
        acc.w += __shfl_down_sync(0xffffffffu, acc.w, d);
    }
    return acc;
}

// ---- agg1: warp-per-node gather (R8 grid shape): ax = dinv*(agg xs) -------
__global__ __launch_bounds__(256) void k_agg1(int n, int e) {
    int warp = (blockIdx.x * blockDim.x + threadIdx.x) >> 5;
    int lane = threadIdx.x & 31;
    if (warp >= n) return;
    int v = warp;
    float4 acc = aggh(g_xsh, v, lane, rp(v, e), rp(v + 1, e));
    if (lane < 8) {
        float dv = g_dinv[v];
        float4 r;
        r.x = dv * acc.x; r.y = dv * acc.y;
        r.z = dv * acc.z; r.w = dv * acc.w;
        *(float4*)&g_ax[v * 32 + lane * 4] = r;
    }
}

// ---- mlp: dedicated, warp owns TILE_W nodes; weights in regs (phased so
// w1p/w2p lifetimes are disjoint); activations via conflict-free LDS.128
// broadcasts. gs = dinv*(relu(ax@W1+b1)@W2) -> fp16.
__global__ __launch_bounds__(256) void k_mlp(const float* __restrict__ W1,
                                             const float* __restrict__ b1,
                                             const float* __restrict__ W2,
                                             int n) {
    __shared__ __align__(16) float s_ax[8][TILE_W][FIN];
    __shared__ __align__(16) float s_h[8][TILE_W][FHID];

    int wl = threadIdx.x >> 5;
    int lane = threadIdx.x & 31;
    int base = (blockIdx.x * 8 + wl) * TILE_W;
    if (base >= n) return;

    // --- A: stage 8 node rows (g_ax is padded; OOB rows unused) ---
    {
        const float4* src = (const float4*)(g_ax + base * 32);
        float4* dst = (float4*)s_ax[wl];
        dst[lane]      = src[lane];
        dst[lane + 32] = src[lane + 32];
    }
    __syncwarp();

    // --- B: layer 1, weight column-pair (lane, lane+32) in registers ---
    {
        unsigned long long w1p[32];
#pragma unroll
        for (int i = 0; i < 32; i++)
            w1p[i] = pk2(W1[i * 64 + lane], W1[i * 64 + 32 + lane]);
        unsigned long long bpair = pk2(b1[lane], b1[lane + 32]);

#pragma unroll 1
        for (int j = 0; j < TILE_W; j++) {
            if (base + j >= n) break;
            unsigned long long acc = bpair;
            const float4* axv = (const float4*)s_ax[wl][j];
#pragma unroll
            for (int i4 = 0; i4 < 8; i4++) {
                float4 x4 = axv[i4];          // LDS.128 broadcast
                FMA2(acc, dup2(x4.x), w1p[i4 * 4 + 0], acc);
                FMA2(acc, dup2(x4.y), w1p[i4 * 4 + 1], acc);
                FMA2(acc, dup2(x4.z), w1p[i4 * 4 + 2], acc);
                FMA2(acc, dup2(x4.w), w1p[i4 * 4 + 3], acc);
            }
            s_h[wl][j][lane]      = fmaxf(lo2(acc), 0.f);
            s_h[wl][j][lane + 32] = fmaxf(hi2(acc), 0.f);
        }
    }
    __syncwarp();

    // --- C: layer 2, weight row-pair (2i, 2i+1) column lane in registers ---
    {
        unsigned long long w2p[32];
#pragma unroll
        for (int i = 0; i < 32; i++)
            w2p[i] = pk2(W2[(2 * i) * 32 + lane], W2[(2 * i + 1) * 32 + lane]);

#pragma unroll 1
        for (int j = 0; j < TILE_W; j++) {
            int v = base + j;
            if (v >= n) break;
            unsigned long long acc = 0;
            const float4* hv = (const float4*)s_h[wl][j];
#pragma unroll
            for (int i4 = 0; i4 < 16; i4++) {
                float4 h4 = hv[i4];           // LDS.128 broadcast
                FMA2(acc, pk2(h4.x, h4.y), w2p[2 * i4 + 0], acc);
                FMA2(acc, pk2(h4.z, h4.w), w2p[2 * i4 + 1], acc);
            }
            float o = lo2(acc) + hi2(acc);
            g_gsh[v * 32 + lane] = __float2half_rn(g_dinv[v] * o);
        }
    }
}

// ---- layer 2: warp-per-node: out = dinv*(agg gs) + b2 ---------------------
__global__ __launch_bounds__(256) void k_l2(float* __restrict__ out,
                                            const float* __restrict__ b2,
                                            int n, int e) {
    int warp = (blockIdx.x * blockDim.x + threadIdx.x) >> 5;
    int lane = threadIdx.x & 31;
    if (warp >= n) return;
    int v = warp;

    float4 acc = aggh(g_gsh, v, lane, rp(v, e), rp(v + 1, e));
    if (lane < 8) {
        float dv = g_dinv[v];
        float4 bq = *(const float4*)(b2 + lane * 4);
        float4 r;
        r.x = dv * acc.x + bq.x;
        r.y = dv * acc.y + bq.y;
        r.z = dv * acc.z + bq.z;
        r.w = dv * acc.w + bq.w;
        *(float4*)(out + v * 32 + lane * 4) = r;
    }
}

// ---------------------------------------------------------------------------
extern "C" void kernel_launch(void* const* d_in, const int* in_sizes, int n_in,
                              void* d_out, int out_size) {
    // Resolve by element count: 3.2M x2 {x, edge_index} (probed on-device);
    // 2048 x2 W1 then W2; 64 b1; 32 b2.
    const void* big[2] = {nullptr, nullptr}; int nbig = 0;
    const float* W[2] = {nullptr, nullptr};  int nw = 0;
    const float* b1 = nullptr;
    const float* b2 = nullptr;
    for (int i = 0; i < n_in; i++) {
        int s = in_sizes[i];
        if (s == NN * FIN) { if (nbig < 2) big[nbig++] = d_in[i]; }
        else if (s == FIN * FHID) { if (nw < 2) W[nw++] = (const float*)d_in[i]; }
        else if (s == FHID) b1 = (const float*)d_in[i];
        else if (s == FOUT) b2 = (const float*)d_in[i];
    }
    const float* W1 = W[0];
    const float* W2 = W[1];
    float* out = (float*)d_out;

    const int n = NN;
    const int e = EE;
    int nb = (n + SCAN_B - 1) / SCAN_B;   // 196

    // zero g_deg via memset node (true device address, NOT the host shadow)
    void* degAddr = nullptr;
    cudaGetSymbolAddress(&degAddr, g_deg);
    cudaMemsetAsync(degAddr, 0, NN * sizeof(int));

    int eThreads = e / 4;
    k_count<<<(eThreads + 255) / 256, 256>>>(big[0], big[1], e);
    k_scan<<<nb, SCAN_B>>>(big[0], big[1], n, nb);
    k_fill<<<(eThreads + 255) / 256, 256>>>(big[0], big[1], e);

    int aggGrid = (n * 32 + 255) / 256;                 // warp per node
    k_agg1<<<aggGrid, 256>>>(n, e);
    int mlpGrid = (n + 8 * TILE_W - 1) / (8 * TILE_W);  // 64 nodes per CTA
    k_mlp<<<mlpGrid, 256>>>(W1, b1, W2, n);
    k_l2<<<aggGrid, 256>>>(out, b2, n, e);
}

// round 13
// speedup vs baseline: 1.4819x; 1.0286x over previous
#include <cuda_runtime.h>
#include <cuda_fp16.h>

// Problem constants (fixed shapes per reference)
#define NN 100000
#define EE 1600000
#define FIN 32
#define FHID 64
#define FOUT 32

#define SCAN_B 512
#define NB_MAX 256   // ceil(100000/512)=196 <= 256
#define TILE_W 8     // nodes per warp in k_mlp

// Scratch (device globals — referenced ONLY from device code; host-side use of
// these symbols resolves to the host shadow object on GB300/ATS).
__device__ int    g_deg[NN];
__device__ int    g_rowptr[NN];        // block-local exclusive prefix of deg
__device__ int    g_cur[NN];           // fill cursor, initialized = g_rowptr
__device__ int    g_bsum[NB_MAX];      // per-block sums -> exclusive after last-block scan
__device__ float  g_dinv[NN];
__device__ int    g_col[EE];
__device__ int    g_scan_done = 0;     // last-block ticket (self-resetting)
__device__ __align__(16) __half g_xsh[NN * FIN];        // dinv[v]*x[v]   (fp16)
__device__ __align__(16) __half g_gsh[NN * FOUT];       // dinv[v]*(h@W2) (fp16)
__device__ __align__(16) float  g_ax[(NN + 64) * FIN];  // dinv*(agg xs)  (fp32, padded)

// packed f32x2 helpers
#define FMA2(d, a, b, c) \
    asm("fma.rn.f32x2 %0, %1, %2, %3;" : "=l"(d) : "l"(a), "l"(b), "l"(c))
__device__ __forceinline__ unsigned long long pk2(float a, float b) {
    float2 t = make_float2(a, b);
    return *(unsigned long long*)&t;
}
__device__ __forceinline__ unsigned long long dup2(float a) {
    unsigned long long r;
    asm("mov.b64 %0, {%1, %1};" : "=l"(r) : "r"(__float_as_uint(a)));
    return r;
}
__device__ __forceinline__ float lo2(unsigned long long v) {
    return __uint_as_float((unsigned)(v & 0xffffffffull));
}
__device__ __forceinline__ float hi2(unsigned long long v) {
    return __uint_as_float((unsigned)(v >> 32));
}

// ---------------------------------------------------------------------------
// Per-warp inline probe: which of {c0,c1} is edge_index? Edge words are
// unsigned < 100000; fp32 normal bit patterns are >= 2^23 or have sign bit.
__device__ __forceinline__ int probe_is_edges(const void* c0) {
    unsigned idx = (threadIdx.x & 31) * 99991u + (blockIdx.x & 1023) * 131u;
    unsigned v = ((const unsigned*)c0)[idx];  // < 3.2M
    return __all_sync(0xffffffffu, v < 100000u);
}

// ---- degree count: 4 edges per thread (int4) ------------------------------
__global__ void k_count(const void* c0, const void* c1, int e) {
    const int* eptr = probe_is_edges(c0) ? (const int*)c0 : (const int*)c1;
    int i = (blockIdx.x * blockDim.x + threadIdx.x) * 4;
    if (i < e) {
        int4 d4 = *(const int4*)(eptr + e + i);
        if ((unsigned)d4.x < (unsigned)NN) atomicAdd(&g_deg[d4.x], 1);
        if ((unsigned)d4.y < (unsigned)NN) atomicAdd(&g_deg[d4.y], 1);
        if ((unsigned)d4.z < (unsigned)NN) atomicAdd(&g_deg[d4.z], 1);
        if ((unsigned)d4.w < (unsigned)NN) atomicAdd(&g_deg[d4.w], 1);
    }
}

// ---- scan: block-exclusive scan of deg + dinv + fp16 pre-scale; the last
// block to finish also scans the 196 block sums (fused scanB).
__global__ __launch_bounds__(SCAN_B) void k_scan(const void* c0, const void* c1,
                                                 int n, int nb) {
    const float* xptr = probe_is_edges(c0) ? (const float*)c1 : (const float*)c0;
    __shared__ int   s[SCAN_B];
    __shared__ float sdinv[SCAN_B];
    __shared__ int   sB[NB_MAX];
    __shared__ bool  amLast;
    int t = threadIdx.x;
    int i = blockIdx.x * SCAN_B + t;
    int v = (i < n) ? g_deg[i] : 0;
    s[t] = v;
    __syncthreads();
    for (int o = 1; o < SCAN_B; o <<= 1) {
        int x = (t >= o) ? s[t - o] : 0;
        __syncthreads();
        s[t] += x;
        __syncthreads();
    }
    float d = rsqrtf((float)(v + 1));          // +1 self-loop
    if (i < n) {
        int excl = s[t] - v;
        g_rowptr[i] = excl;
        g_cur[i] = excl;                        // fill cursor
        g_dinv[i] = d;
    }
    sdinv[t] = d;
    if (t == SCAN_B - 1) g_bsum[blockIdx.x] = s[t];
    __syncthreads();

    // pre-scale: nodes [b0, b0+512) -> fp16 rows (4096 quads, 8 iters)
    int b0 = blockIdx.x * SCAN_B;
#pragma unroll
    for (int r = 0; r < 8; r++) {
        int ql = t + r * SCAN_B;               // local quad 0..4095
        int nl = ql >> 3;                      // local node
        int node = b0 + nl;
        if (node < n) {
            float4 p = ((const float4*)xptr)[node * 8 + (ql & 7)];
            float dd = sdinv[nl];
            __half2 h0 = __floats2half2_rn(p.x * dd, p.y * dd);
            __half2 h1 = __floats2half2_rn(p.z * dd, p.w * dd);
            uint2 packed;
            packed.x = *(unsigned*)&h0;
            packed.y = *(unsigned*)&h1;
            ((uint2*)g_xsh)[node * 8 + (ql & 7)] = packed;
        }
    }

    // last-block: exclusive scan of the nb block sums
    __threadfence();
    __syncthreads();
    if (t == 0) amLast = (atomicAdd(&g_scan_done, 1) == gridDim.x - 1);
    __syncthreads();
    if (amLast) {
        __threadfence();                        // acquire all bsum writes
        int bv = (t < NB_MAX && t < nb) ? g_bsum[t] : 0;
        if (t < NB_MAX) sB[t] = bv;
        __syncthreads();
        for (int o = 1; o < NB_MAX; o <<= 1) {
            int x = (t >= o && t < NB_MAX) ? sB[t - o] : 0;
            __syncthreads();
            if (t < NB_MAX) sB[t] += x;
            __syncthreads();
        }
        if (t < nb) g_bsum[t] = sB[t] - bv;     // exclusive block offsets
        if (t == 0) g_scan_done = 0;            // reset for next graph replay
    }
}

// global rowptr on the fly
__device__ __forceinline__ int rp(int i, int e) {
    return (i == NN) ? e : (g_rowptr[i] + g_bsum[i >> 9]);
}

// ---- CSR bucket fill: 4 edges per thread ----------------------------------
__global__ void k_fill(const void* c0, const void* c1, int e) {
    const int* eptr = probe_is_edges(c0) ? (const int*)c0 : (const int*)c1;
    int i = (blockIdx.x * blockDim.x + threadIdx.x) * 4;
    if (i < e) {
        int4 s4 = *(const int4*)(eptr + i);
        int4 d4 = *(const int4*)(eptr + e + i);
        if ((unsigned)d4.x < (unsigned)NN)
            g_col[atomicAdd(&g_cur[d4.x], 1) + g_bsum[d4.x >> 9]] = s4.x;
        if ((unsigned)d4.y < (unsigned)NN)
            g_col[atomicAdd(&g_cur[d4.y], 1) + g_bsum[d4.y >> 9]] = s4.y;
        if ((unsigned)d4.z < (unsigned)NN)
            g_col[atomicAdd(&g_cur[d4.z], 1) + g_bsum[d4.z >> 9]] = s4.z;
        if ((unsigned)d4.w < (unsigned)NN)
            g_col[atomicAdd(&g_cur[d4.w], 1) + g_bsum[d4.w >> 9]] = s4.w;
    }
}

// ---- fp16 warp aggregation core v3: prefetched indices ---------------------
// Warp = node v. lane = eslot(2b)<<3 | fq(3b). Per 32-edge batch, ONE
// coalesced LDG loads all column indices into registers (lane i holds edge
// beg+i); each 4-edge group gets its index via SHFL.IDX, so the gather LDGs
// are address-independent of each other and of any other load -> their
// latencies overlap instead of chaining. Remainder handled once per node.
// After reduce, lanes 0..7 hold quad fq of sum_{u in N(v)} in[u] + in[v].
__device__ __forceinline__ float4 aggh(const __half* __restrict__ in,
                                       int v, int lane, int beg, int end) {
    int eslot = lane >> 3;
    int fq = lane & 7;
    float4 acc = make_float4(0.f, 0.f, 0.f, 0.f);
    for (int b = beg; b < end; b += 32) {
        int li = b + lane;
        int myu = (li < end) ? g_col[li] : 0;    // one coalesced index load
        int m = min(32, end - b);                // edges this batch
        int ng = m >> 2;                         // full groups of 4
        for (int g = 0; g < ng; g++) {
            int u = __shfl_sync(0xffffffffu, myu, g * 4 + eslot);
            uint2 raw = *(const uint2*)(in + u * 32 + fq * 4);
            float2 fa = __half22float2(*(__half2*)&raw.x);
            float2 fb = __half22float2(*(__half2*)&raw.y);
            acc.x += fa.x; acc.y += fa.y; acc.z += fb.x; acc.w += fb.y;
        }
        int r = m & 3;                           // 0..3 leftover edges
        if (r) {
            int src = ng * 4 + ((eslot < r) ? eslot : 0);
            int u = __shfl_sync(0xffffffffu, myu, src);
            if (eslot < r) {
                uint2 raw = *(const uint2*)(in + u * 32 + fq * 4);
                float2 fa = __half22float2(*(__half2*)&raw.x);
                float2 fb = __half22float2(*(__half2*)&raw.y);
                acc.x += fa.x; acc.y += fa.y; acc.z += fb.x; acc.w += fb.y;
            }
        }
    }
    if (eslot == 0) {   // self-loop (inputs pre-scaled by dinv)
        uint2 raw = *(const uint2*)(in + v * 32 + fq * 4);
        float2 fa = __half22float2(*(__half2*)&raw.x);
        float2 fb = __half22float2(*(__half2*)&raw.y);
        acc.x += fa.x; acc.y += fa.y; acc.z += fb.x; acc.w += fb.y;
    }
#pragma unroll
    for (int d = 16; d >= 8; d >>= 1) {
        acc.x += __shfl_down_sync(0xffffffffu, acc.x, d);
        acc.y += __shfl_down_sync(0xffffffffu, acc.y, d);
        acc.z += __shfl_down_sync(0xffffffffu, acc.z, d);
        acc.w += __shfl_down_sync(0xffffffffu, acc.w, d);
    }
    return acc;
}

// ---- agg1: warp-per-node gather: ax = dinv*(agg xs) -----------------------
__global__ __launch_bounds__(256) void k_agg1(int n, int e) {
    int warp = (blockIdx.x * blockDim.x + threadIdx.x) >> 5;
    int lane = threadIdx.x & 31;
    if (warp >= n) return;
    int v = warp;
    float4 acc = aggh(g_xsh, v, lane, rp(v, e), rp(v + 1, e));
    if (lane < 8) {
        float dv = g_dinv[v];
        float4 r;
        r.x = dv * acc.x; r.y = dv * acc.y;
        r.z = dv * acc.z; r.w = dv * acc.w;
        *(float4*)&g_ax[v * 32 + lane * 4] = r;
    }
}

// ---- mlp: dedicated, warp owns TILE_W nodes; weights in regs (phased so
// w1p/w2p lifetimes are disjoint); activations via conflict-free LDS.128
// broadcasts. gs = dinv*(relu(ax@W1+b1)@W2) -> fp16.
__global__ __launch_bounds__(256) void k_mlp(const float* __restrict__ W1,
                                             const float* __restrict__ b1,
                                             const float* __restrict__ W2,
                                             int n) {
    __shared__ __align__(16) float s_ax[8][TILE_W][FIN];
    __shared__ __align__(16) float s_h[8][TILE_W][FHID];

    int wl = threadIdx.x >> 5;
    int lane = threadIdx.x & 31;
    int base = (blockIdx.x * 8 + wl) * TILE_W;
    if (base >= n) return;

    // --- A: stage 8 node rows (g_ax is padded; OOB rows unused) ---
    {
        const float4* src = (const float4*)(g_ax + base * 32);
        float4* dst = (float4*)s_ax[wl];
        dst[lane]      = src[lane];
        dst[lane + 32] = src[lane + 32];
    }
    __syncwarp();

    // --- B: layer 1, weight column-pair (lane, lane+32) in registers ---
    {
        unsigned long long w1p[32];
#pragma unroll
        for (int i = 0; i < 32; i++)
            w1p[i] = pk2(W1[i * 64 + lane], W1[i * 64 + 32 + lane]);
        unsigned long long bpair = pk2(b1[lane], b1[lane + 32]);

#pragma unroll 1
        for (int j = 0; j < TILE_W; j++) {
            if (base + j >= n) break;
            unsigned long long acc = bpair;
            const float4* axv = (const float4*)s_ax[wl][j];
#pragma unroll
            for (int i4 = 0; i4 < 8; i4++) {
                float4 x4 = axv[i4];          // LDS.128 broadcast
                FMA2(acc, dup2(x4.x), w1p[i4 * 4 + 0], acc);
                FMA2(acc, dup2(x4.y), w1p[i4 * 4 + 1], acc);
                FMA2(acc, dup2(x4.z), w1p[i4 * 4 + 2], acc);
                FMA2(acc, dup2(x4.w), w1p[i4 * 4 + 3], acc);
            }
            s_h[wl][j][lane]      = fmaxf(lo2(acc), 0.f);
            s_h[wl][j][lane + 32] = fmaxf(hi2(acc), 0.f);
        }
    }
    __syncwarp();

    // --- C: layer 2, weight row-pair (2i, 2i+1) column lane in registers ---
    {
        unsigned long long w2p[32];
#pragma unroll
        for (int i = 0; i < 32; i++)
            w2p[i] = pk2(W2[(2 * i) * 32 + lane], W2[(2 * i + 1) * 32 + lane]);

#pragma unroll 1
        for (int j = 0; j < TILE_W; j++) {
            int v = base + j;
            if (v >= n) break;
            unsigned long long acc = 0;
            const float4* hv = (const float4*)s_h[wl][j];
#pragma unroll
            for (int i4 = 0; i4 < 16; i4++) {
                float4 h4 = hv[i4];           // LDS.128 broadcast
                FMA2(acc, pk2(h4.x, h4.y), w2p[2 * i4 + 0], acc);
                FMA2(acc, pk2(h4.z, h4.w), w2p[2 * i4 + 1], acc);
            }
            float o = lo2(acc) + hi2(acc);
            g_gsh[v * 32 + lane] = __float2half_rn(g_dinv[v] * o);
        }
    }
}

// ---- layer 2: warp-per-node: out = dinv*(agg gs) + b2 ---------------------
__global__ __launch_bounds__(256) void k_l2(float* __restrict__ out,
                                            const float* __restrict__ b2,
                                            int n, int e) {
    int warp = (blockIdx.x * blockDim.x + threadIdx.x) >> 5;
    int lane = threadIdx.x & 31;
    if (warp >= n) return;
    int v = warp;

    float4 acc = aggh(g_gsh, v, lane, rp(v, e), rp(v + 1, e));
    if (lane < 8) {
        float dv = g_dinv[v];
        float4 bq = *(const float4*)(b2 + lane * 4);
        float4 r;
        r.x = dv * acc.x + bq.x;
        r.y = dv * acc.y + bq.y;
        r.z = dv * acc.z + bq.z;
        r.w = dv * acc.w + bq.w;
        *(float4*)(out + v * 32 + lane * 4) = r;
    }
}

// ---------------------------------------------------------------------------
extern "C" void kernel_launch(void* const* d_in, const int* in_sizes, int n_in,
                              void* d_out, int out_size) {
    // Resolve by element count: 3.2M x2 {x, edge_index} (probed on-device);
    // 2048 x2 W1 then W2; 64 b1; 32 b2.
    const void* big[2] = {nullptr, nullptr}; int nbig = 0;
    const float* W[2] = {nullptr, nullptr};  int nw = 0;
    const float* b1 = nullptr;
    const float* b2 = nullptr;
    for (int i = 0; i < n_in; i++) {
        int s = in_sizes[i];
        if (s == NN * FIN) { if (nbig < 2) big[nbig++] = d_in[i]; }
        else if (s == FIN * FHID) { if (nw < 2) W[nw++] = (const float*)d_in[i]; }
        else if (s == FHID) b1 = (const float*)d_in[i];
        else if (s == FOUT) b2 = (const float*)d_in[i];
    }
    const float* W1 = W[0];
    const float* W2 = W[1];
    float* out = (float*)d_out;

    const int n = NN;
    const int e = EE;
    int nb = (n + SCAN_B - 1) / SCAN_B;   // 196

    // zero g_deg via memset node (true device address, NOT the host shadow)
    void* degAddr = nullptr;
    cudaGetSymbolAddress(&degAddr, g_deg);
    cudaMemsetAsync(degAddr, 0, NN * sizeof(int));

    int eThreads = e / 4;
    k_count<<<(eThreads + 255) / 256, 256>>>(big[0], big[1], e);
    k_scan<<<nb, SCAN_B>>>(big[0], big[1], n, nb);
    k_fill<<<(eThreads + 255) / 256, 256>>>(big[0], big[1], e);

    int aggGrid = (n * 32 + 255) / 256;                 // warp per node
    k_agg1<<<aggGrid, 256>>>(n, e);
    int mlpGrid = (n + 8 * TILE_W - 1) / (8 * TILE_W);  // 64 nodes per CTA
    k_mlp<<<mlpGrid, 256>>>(W1, b1, W2, n);
    k_l2<<<aggGrid, 256>>>(out, b2, n, e);
}

// round 14
// speedup vs baseline: 1.5561x; 1.0501x over previous
#include <cuda_runtime.h>
#include <cuda_fp16.h>

// Problem constants (fixed shapes per reference)
#define NN 100000
#define EE 1600000
#define FIN 32
#define FHID 64
#define FOUT 32

#define SCAN_B 512
#define NB_MAX 256   // ceil(100000/512)=196 <= 256
#define TILE_W 8     // nodes per warp in k_mlp

// Scratch (device globals — referenced ONLY from device code; host-side use of
// these symbols resolves to the host shadow object on GB300/ATS).
__device__ int    g_deg[NN];
__device__ int    g_rowptr[NN];        // block-local exclusive prefix of deg
__device__ int    g_cur[NN];           // fill cursor, initialized = g_rowptr
__device__ int    g_bsum[NB_MAX];      // per-block sums -> exclusive after last-block scan
__device__ float  g_dinv[NN];
__device__ int    g_col[EE];
__device__ int    g_scan_done = 0;     // last-block ticket (self-resetting)
__device__ __align__(16) __half g_xsh[NN * FIN];        // dinv[v]*x[v]   (fp16)
__device__ __align__(16) __half g_gsh[NN * FOUT];       // dinv[v]*(h@W2) (fp16)
__device__ __align__(16) float  g_ax[(NN + 64) * FIN];  // dinv*(agg xs)  (fp32, padded)

// packed f32x2 helpers
#define FMA2(d, a, b, c) \
    asm("fma.rn.f32x2 %0, %1, %2, %3;" : "=l"(d) : "l"(a), "l"(b), "l"(c))
__device__ __forceinline__ unsigned long long pk2(float a, float b) {
    float2 t = make_float2(a, b);
    return *(unsigned long long*)&t;
}
__device__ __forceinline__ unsigned long long dup2(float a) {
    unsigned long long r;
    asm("mov.b64 %0, {%1, %1};" : "=l"(r) : "r"(__float_as_uint(a)));
    return r;
}
__device__ __forceinline__ float lo2(unsigned long long v) {
    return __uint_as_float((unsigned)(v & 0xffffffffull));
}
__device__ __forceinline__ float hi2(unsigned long long v) {
    return __uint_as_float((unsigned)(v >> 32));
}

// ---------------------------------------------------------------------------
// Per-warp inline probe: which of {c0,c1} is edge_index? Edge words are
// unsigned < 100000; fp32 normal bit patterns are >= 2^23 or have sign bit.
__device__ __forceinline__ int probe_is_edges(const void* c0) {
    unsigned idx = (threadIdx.x & 31) * 99991u + (blockIdx.x & 1023) * 131u;
    unsigned v = ((const unsigned*)c0)[idx];  // < 3.2M
    return __all_sync(0xffffffffu, v < 100000u);
}

// ---- degree count: 4 edges per thread (int4) ------------------------------
__global__ void k_count(const void* c0, const void* c1, int e) {
    const int* eptr = probe_is_edges(c0) ? (const int*)c0 : (const int*)c1;
    int i = (blockIdx.x * blockDim.x + threadIdx.x) * 4;
    if (i < e) {
        int4 d4 = *(const int4*)(eptr + e + i);
        if ((unsigned)d4.x < (unsigned)NN) atomicAdd(&g_deg[d4.x], 1);
        if ((unsigned)d4.y < (unsigned)NN) atomicAdd(&g_deg[d4.y], 1);
        if ((unsigned)d4.z < (unsigned)NN) atomicAdd(&g_deg[d4.z], 1);
        if ((unsigned)d4.w < (unsigned)NN) atomicAdd(&g_deg[d4.w], 1);
    }
}

// ---- scan: block-exclusive scan of deg + dinv + fp16 pre-scale; the last
// block to finish also scans the 196 block sums (fused scanB).
__global__ __launch_bounds__(SCAN_B) void k_scan(const void* c0, const void* c1,
                                                 int n, int nb) {
    const float* xptr = probe_is_edges(c0) ? (const float*)c1 : (const float*)c0;
    __shared__ int   s[SCAN_B];
    __shared__ float sdinv[SCAN_B];
    __shared__ int   sB[NB_MAX];
    __shared__ bool  amLast;
    int t = threadIdx.x;
    int i = blockIdx.x * SCAN_B + t;
    int v = (i < n) ? g_deg[i] : 0;
    s[t] = v;
    __syncthreads();
    for (int o = 1; o < SCAN_B; o <<= 1) {
        int x = (t >= o) ? s[t - o] : 0;
        __syncthreads();
        s[t] += x;
        __syncthreads();
    }
    float d = rsqrtf((float)(v + 1));          // +1 self-loop
    if (i < n) {
        int excl = s[t] - v;
        g_rowptr[i] = excl;
        g_cur[i] = excl;                        // fill cursor
        g_dinv[i] = d;
    }
    sdinv[t] = d;
    if (t == SCAN_B - 1) g_bsum[blockIdx.x] = s[t];
    __syncthreads();

    // pre-scale: nodes [b0, b0+512) -> fp16 rows (4096 quads, 8 iters)
    int b0 = blockIdx.x * SCAN_B;
#pragma unroll
    for (int r = 0; r < 8; r++) {
        int ql = t + r * SCAN_B;               // local quad 0..4095
        int nl = ql >> 3;                      // local node
        int node = b0 + nl;
        if (node < n) {
            float4 p = ((const float4*)xptr)[node * 8 + (ql & 7)];
            float dd = sdinv[nl];
            __half2 h0 = __floats2half2_rn(p.x * dd, p.y * dd);
            __half2 h1 = __floats2half2_rn(p.z * dd, p.w * dd);
            uint2 packed;
            packed.x = *(unsigned*)&h0;
            packed.y = *(unsigned*)&h1;
            ((uint2*)g_xsh)[node * 8 + (ql & 7)] = packed;
        }
    }

    // last-block: exclusive scan of the nb block sums
    __threadfence();
    __syncthreads();
    if (t == 0) amLast = (atomicAdd(&g_scan_done, 1) == gridDim.x - 1);
    __syncthreads();
    if (amLast) {
        __threadfence();                        // acquire all bsum writes
        int bv = (t < NB_MAX && t < nb) ? g_bsum[t] : 0;
        if (t < NB_MAX) sB[t] = bv;
        __syncthreads();
        for (int o = 1; o < NB_MAX; o <<= 1) {
            int x = (t >= o && t < NB_MAX) ? sB[t - o] : 0;
            __syncthreads();
            if (t < NB_MAX) sB[t] += x;
            __syncthreads();
        }
        if (t < nb) g_bsum[t] = sB[t] - bv;     // exclusive block offsets
        if (t == 0) g_scan_done = 0;            // reset for next graph replay
    }
}

// global rowptr on the fly
__device__ __forceinline__ int rp(int i, int e) {
    return (i == NN) ? e : (g_rowptr[i] + g_bsum[i >> 9]);
}

// ---- CSR bucket fill: 4 edges per thread ----------------------------------
__global__ void k_fill(const void* c0, const void* c1, int e) {
    const int* eptr = probe_is_edges(c0) ? (const int*)c0 : (const int*)c1;
    int i = (blockIdx.x * blockDim.x + threadIdx.x) * 4;
    if (i < e) {
        int4 s4 = *(const int4*)(eptr + i);
        int4 d4 = *(const int4*)(eptr + e + i);
        if ((unsigned)d4.x < (unsigned)NN)
            g_col[atomicAdd(&g_cur[d4.x], 1) + g_bsum[d4.x >> 9]] = s4.x;
        if ((unsigned)d4.y < (unsigned)NN)
            g_col[atomicAdd(&g_cur[d4.y], 1) + g_bsum[d4.y >> 9]] = s4.y;
        if ((unsigned)d4.z < (unsigned)NN)
            g_col[atomicAdd(&g_cur[d4.z], 1) + g_bsum[d4.z >> 9]] = s4.z;
        if ((unsigned)d4.w < (unsigned)NN)
            g_col[atomicAdd(&g_cur[d4.w], 1) + g_bsum[d4.w >> 9]] = s4.w;
    }
}

// ---- fp16 warp aggregation core (R8 style, widened): 16 edges/iteration ---
// Warp = node v. lane = eslot(2b)<<3 | fq(3b). Per iteration each lane
// issues up to 4 independent col loads and 4 independent 8B gathers (4
// parallel col->gather chains, R8 had 2). Tail handled by the same
// predicated guards as R8. After reduce, lanes 0..7 hold quad fq of
//   sum_{u in N(v)} in[u] + in[v]   (inputs pre-scaled by dinv[u]).
__device__ __forceinline__ float4 aggh(const __half* __restrict__ in,
                                       int v, int lane, int beg, int end) {
    int eslot = lane >> 3;
    int fq = lane & 7;
    float4 acc = make_float4(0.f, 0.f, 0.f, 0.f);
    for (int k = beg; k < end; k += 16) {
        int i0 = k + eslot;
        int i1 = i0 + 4;
        int i2 = i0 + 8;
        int i3 = i0 + 12;
        int u0 = (i0 < end) ? g_col[i0] : -1;
        int u1 = (i1 < end) ? g_col[i1] : -1;
        int u2 = (i2 < end) ? g_col[i2] : -1;
        int u3 = (i3 < end) ? g_col[i3] : -1;
        if (u0 >= 0) {
            uint2 raw = *(const uint2*)(in + u0 * 32 + fq * 4);
            float2 fa = __half22float2(*(__half2*)&raw.x);
            float2 fb = __half22float2(*(__half2*)&raw.y);
            acc.x += fa.x; acc.y += fa.y; acc.z += fb.x; acc.w += fb.y;
        }
        if (u1 >= 0) {
            uint2 raw = *(const uint2*)(in + u1 * 32 + fq * 4);
            float2 fa = __half22float2(*(__half2*)&raw.x);
            float2 fb = __half22float2(*(__half2*)&raw.y);
            acc.x += fa.x; acc.y += fa.y; acc.z += fb.x; acc.w += fb.y;
        }
        if (u2 >= 0) {
            uint2 raw = *(const uint2*)(in + u2 * 32 + fq * 4);
            float2 fa = __half22float2(*(__half2*)&raw.x);
            float2 fb = __half22float2(*(__half2*)&raw.y);
            acc.x += fa.x; acc.y += fa.y; acc.z += fb.x; acc.w += fb.y;
        }
        if (u3 >= 0) {
            uint2 raw = *(const uint2*)(in + u3 * 32 + fq * 4);
            float2 fa = __half22float2(*(__half2*)&raw.x);
            float2 fb = __half22float2(*(__half2*)&raw.y);
            acc.x += fa.x; acc.y += fa.y; acc.z += fb.x; acc.w += fb.y;
        }
    }
    if (eslot == 0) {   // self-loop
        uint2 raw = *(const uint2*)(in + v * 32 + fq * 4);
        float2 fa = __half22float2(*(__half2*)&raw.x);
        float2 fb = __half22float2(*(__half2*)&raw.y);
        acc.x += fa.x; acc.y += fa.y; acc.z += fb.x; acc.w += fb.y;
    }
#pragma unroll
    for (int d = 16; d >= 8; d >>= 1) {
        acc.x += __shfl_down_sync(0xffffffffu, acc.x, d);
        acc.y += __shfl_down_sync(0xffffffffu, acc.y, d);
        acc.z += __shfl_down_sync(0xffffffffu, acc.z, d);
        acc.w += __shfl_down_sync(0xffffffffu, acc.w, d);
    }
    return acc;
}

// ---- agg1: warp-per-node gather: ax = dinv*(agg xs) -----------------------
__global__ __launch_bounds__(256) void k_agg1(int n, int e) {
    int warp = (blockIdx.x * blockDim.x + threadIdx.x) >> 5;
    int lane = threadIdx.x & 31;
    if (warp >= n) return;
    int v = warp;
    float4 acc = aggh(g_xsh, v, lane, rp(v, e), rp(v + 1, e));
    if (lane < 8) {
        float dv = g_dinv[v];
        float4 r;
        r.x = dv * acc.x; r.y = dv * acc.y;
        r.z = dv * acc.z; r.w = dv * acc.w;
        *(float4*)&g_ax[v * 32 + lane * 4] = r;
    }
}

// ---- mlp: dedicated, warp owns TILE_W nodes; weights in regs (phased so
// w1p/w2p lifetimes are disjoint); activations via conflict-free LDS.128
// broadcasts. gs = dinv*(relu(ax@W1+b1)@W2) -> fp16.
__global__ __launch_bounds__(256) void k_mlp(const float* __restrict__ W1,
                                             const float* __restrict__ b1,
                                             const float* __restrict__ W2,
                                             int n) {
    __shared__ __align__(16) float s_ax[8][TILE_W][FIN];
    __shared__ __align__(16) float s_h[8][TILE_W][FHID];

    int wl = threadIdx.x >> 5;
    int lane = threadIdx.x & 31;
    int base = (blockIdx.x * 8 + wl) * TILE_W;
    if (base >= n) return;

    // --- A: stage 8 node rows (g_ax is padded; OOB rows unused) ---
    {
        const float4* src = (const float4*)(g_ax + base * 32);
        float4* dst = (float4*)s_ax[wl];
        dst[lane]      = src[lane];
        dst[lane + 32] = src[lane + 32];
    }
    __syncwarp();

    // --- B: layer 1, weight column-pair (lane, lane+32) in registers ---
    {
        unsigned long long w1p[32];
#pragma unroll
        for (int i = 0; i < 32; i++)
            w1p[i] = pk2(W1[i * 64 + lane], W1[i * 64 + 32 + lane]);
        unsigned long long bpair = pk2(b1[lane], b1[lane + 32]);

#pragma unroll 1
        for (int j = 0; j < TILE_W; j++) {
            if (base + j >= n) break;
            unsigned long long acc = bpair;
            const float4* axv = (const float4*)s_ax[wl][j];
#pragma unroll
            for (int i4 = 0; i4 < 8; i4++) {
                float4 x4 = axv[i4];          // LDS.128 broadcast
                FMA2(acc, dup2(x4.x), w1p[i4 * 4 + 0], acc);
                FMA2(acc, dup2(x4.y), w1p[i4 * 4 + 1], acc);
                FMA2(acc, dup2(x4.z), w1p[i4 * 4 + 2], acc);
                FMA2(acc, dup2(x4.w), w1p[i4 * 4 + 3], acc);
            }
            s_h[wl][j][lane]      = fmaxf(lo2(acc), 0.f);
            s_h[wl][j][lane + 32] = fmaxf(hi2(acc), 0.f);
        }
    }
    __syncwarp();

    // --- C: layer 2, weight row-pair (2i, 2i+1) column lane in registers ---
    {
        unsigned long long w2p[32];
#pragma unroll
        for (int i = 0; i < 32; i++)
            w2p[i] = pk2(W2[(2 * i) * 32 + lane], W2[(2 * i + 1) * 32 + lane]);

#pragma unroll 1
        for (int j = 0; j < TILE_W; j++) {
            int v = base + j;
            if (v >= n) break;
            unsigned long long acc = 0;
            const float4* hv = (const float4*)s_h[wl][j];
#pragma unroll
            for (int i4 = 0; i4 < 16; i4++) {
                float4 h4 = hv[i4];           // LDS.128 broadcast
                FMA2(acc, pk2(h4.x, h4.y), w2p[2 * i4 + 0], acc);
                FMA2(acc, pk2(h4.z, h4.w), w2p[2 * i4 + 1], acc);
            }
            float o = lo2(acc) + hi2(acc);
            g_gsh[v * 32 + lane] = __float2half_rn(g_dinv[v] * o);
        }
    }
}

// ---- layer 2: warp-per-node: out = dinv*(agg gs) + b2 ---------------------
__global__ __launch_bounds__(256) void k_l2(float* __restrict__ out,
                                            const float* __restrict__ b2,
                                            int n, int e) {
    int warp = (blockIdx.x * blockDim.x + threadIdx.x) >> 5;
    int lane = threadIdx.x & 31;
    if (warp >= n) return;
    int v = warp;

    float4 acc = aggh(g_gsh, v, lane, rp(v, e), rp(v + 1, e));
    if (lane < 8) {
        float dv = g_dinv[v];
        float4 bq = *(const float4*)(b2 + lane * 4);
        float4 r;
        r.x = dv * acc.x + bq.x;
        r.y = dv * acc.y + bq.y;
        r.z = dv * acc.z + bq.z;
        r.w = dv * acc.w + bq.w;
        *(float4*)(out + v * 32 + lane * 4) = r;
    }
}

// ---------------------------------------------------------------------------
extern "C" void kernel_launch(void* const* d_in, const int* in_sizes, int n_in,
                              void* d_out, int out_size) {
    // Resolve by element count: 3.2M x2 {x, edge_index} (probed on-device);
    // 2048 x2 W1 then W2; 64 b1; 32 b2.
    const void* big[2] = {nullptr, nullptr}; int nbig = 0;
    const float* W[2] = {nullptr, nullptr};  int nw = 0;
    const float* b1 = nullptr;
    const float* b2 = nullptr;
    for (int i = 0; i < n_in; i++) {
        int s = in_sizes[i];
        if (s == NN * FIN) { if (nbig < 2) big[nbig++] = d_in[i]; }
        else if (s == FIN * FHID) { if (nw < 2) W[nw++] = (const float*)d_in[i]; }
        else if (s == FHID) b1 = (const float*)d_in[i];
        else if (s == FOUT) b2 = (const float*)d_in[i];
    }
    const float* W1 = W[0];
    const float* W2 = W[1];
    float* out = (float*)d_out;

    const int n = NN;
    const int e = EE;
    int nb = (n + SCAN_B - 1) / SCAN_B;   // 196

    // zero g_deg via memset node (true device address, NOT the host shadow)
    void* degAddr = nullptr;
    cudaGetSymbolAddress(&degAddr, g_deg);
    cudaMemsetAsync(degAddr, 0, NN * sizeof(int));

    int eThreads = e / 4;
    k_count<<<(eThreads + 255) / 256, 256>>>(big[0], big[1], e);
    k_scan<<<nb, SCAN_B>>>(big[0], big[1], n, nb);
    k_fill<<<(eThreads + 255) / 256, 256>>>(big[0], big[1], e);

    int aggGrid = (n * 32 + 255) / 256;                 // warp per node
    k_agg1<<<aggGrid, 256>>>(n, e);
    int mlpGrid = (n + 8 * TILE_W - 1) / (8 * TILE_W);  // 64 nodes per CTA
    k_mlp<<<mlpGrid, 256>>>(W1, b1, W2, n);
    k_l2<<<aggGrid, 256>>>(out, b2, n, e);
}